// round 8
// baseline (speedup 1.0000x reference)
#include <cuda_runtime.h>

// ============================================================================
// FastAsyncGNN: 3-layer GCN
//   zero-deg -> count -> scan -> fill -> [GEMM -> agg]x2 -> GEMM3(+bias)
// Shapes: N=50000, E=800000, F_IN=128, F_HID=96, F_OUT=40
// ============================================================================

#define NN 50000
#define EE 800000

// -------- scratch (device globals; no allocation allowed) --------
__device__ int   g_deg[NN];        // raw in-edge count (no self loop)
__device__ int   g_cur[NN];        // fill cursors
__device__ int   g_rowptr[NN + 1]; // CSR row pointers (real edges only)
__device__ float g_dinv[NN];       // rsqrt(deg+1)
__device__ __align__(8)  int2  g_cw[EE];      // (src, wgt-bits) per CSR slot
__device__ __align__(16) float g_h[NN * 96];  // GEMM output buffer
__device__ __align__(16) float g_a[NN * 96];  // aggregated/activated buffer

// ============================================================================
// packed f32x2 helpers
// ============================================================================
__device__ __forceinline__ unsigned long long pack2(float lo, float hi) {
    unsigned long long r;
    asm("mov.b64 %0, {%1, %2};" : "=l"(r) : "f"(lo), "f"(hi));
    return r;
}
__device__ __forceinline__ void unpack2(unsigned long long v, float& lo, float& hi) {
    asm("mov.b64 {%0, %1}, %2;" : "=f"(lo), "=f"(hi) : "l"(v));
}
#define FMA_F32X2(d, a, b) \
    asm("fma.rn.f32x2 %0, %1, %2, %0;" : "+l"(d) : "l"(a), "l"(b))

// ============================================================================
// CSR build
// ============================================================================
__global__ void zero_deg_kernel() {
    int i = blockIdx.x * blockDim.x + threadIdx.x;
    if (i < NN) g_deg[i] = 0;
}

__global__ void count_kernel(const int* __restrict__ dst) {
    int e = blockIdx.x * blockDim.x + threadIdx.x;
    if (e < EE) atomicAdd(&g_deg[dst[e]], 1);
}

// single block, 1024 threads: exclusive scan of deg; dinv; zero cursors
__global__ void scan_kernel() {
    __shared__ int s[1024];
    int tid = threadIdx.x;
    const int per = (NN + 1023) / 1024;  // 49
    int start = tid * per;
    int end = start + per; if (end > NN) end = NN;
    int sum = 0;
    for (int i = start; i < end; i++) sum += g_deg[i];
    s[tid] = sum;
    __syncthreads();
    for (int off = 1; off < 1024; off <<= 1) {
        int v = s[tid];
        int u = (tid >= off) ? s[tid - off] : 0;
        __syncthreads();
        s[tid] = v + u;
        __syncthreads();
    }
    int run = (tid > 0) ? s[tid - 1] : 0;
    for (int i = start; i < end; i++) {
        g_rowptr[i] = run;
        run += g_deg[i];
        g_dinv[i] = rsqrtf((float)(g_deg[i] + 1));
        g_cur[i] = 0;
    }
    if (tid == 1023) g_rowptr[NN] = s[1023];
}

// 2 edges per thread (independent latency chains), int2 coalesced loads
__global__ void fill_kernel(const int* __restrict__ src, const int* __restrict__ dst) {
    int t = blockIdx.x * blockDim.x + threadIdx.x;
    int e0 = t * 2;
    if (e0 + 1 < EE) {
        int2 sp = *(const int2*)(src + e0);
        int2 dp = *(const int2*)(dst + e0);
        int p0 = atomicAdd(&g_cur[dp.x], 1);
        int p1 = atomicAdd(&g_cur[dp.y], 1);
        int o0 = g_rowptr[dp.x] + p0;
        int o1 = g_rowptr[dp.y] + p1;
        g_cw[o0] = make_int2(sp.x, __float_as_int(g_dinv[sp.x] * g_dinv[dp.x]));
        g_cw[o1] = make_int2(sp.y, __float_as_int(g_dinv[sp.y] * g_dinv[dp.y]));
    } else if (e0 < EE) {
        int sN = src[e0];
        int d = dst[e0];
        int p = atomicAdd(&g_cur[d], 1);
        g_cw[g_rowptr[d] + p] = make_int2(sN, __float_as_int(g_dinv[sN] * g_dinv[d]));
    }
}

// ============================================================================
// GEMM: C[n,FO] = A[n,FI] @ W[FI,FO] (+bias), packed f32x2 inner loop.
// BM = RT*TM = 128 rows, BK = 32. TN even.
// ============================================================================
template <int FI, int FO, int CT, int TN, int RT, int TM, bool BIAS>
__global__ void __launch_bounds__(256)
gemm_kernel(const float* __restrict__ A_, const float* __restrict__ W,
            const float* __restrict__ bias, float* __restrict__ C_, int n) {
    constexpr int BM = RT * TM;  // 128
    constexpr int BK = 32;
    constexpr int NC2 = TN / 2;
    static_assert(CT * RT == 256, "thread shape");
    static_assert(CT * TN == FO, "col coverage");
    static_assert(TN % 2 == 0, "packed cols");
    static_assert(FO % 4 == 0, "W vec4 staging");

    const float* A = A_ ? A_ : (const float*)g_a;
    float* C = C_ ? C_ : (float*)g_h;

    __shared__ float As[BK][BM + 4];   // [kk][row], 528B row stride
    __shared__ float Ws[BK][FO];       // [kk][col]

    int tid = threadIdx.x;
    int tx = tid % CT;
    int ty = tid / CT;
    int row0 = blockIdx.x * BM;

    unsigned long long acc2[TM][NC2];
#pragma unroll
    for (int r = 0; r < TM; r++)
#pragma unroll
        for (int c = 0; c < NC2; c++) acc2[r][c] = 0ull;

    constexpr int A4 = BM * (BK / 4);   // float4s in A tile
    constexpr int W4 = BK * (FO / 4);   // float4s in W tile

    for (int k0 = 0; k0 < FI; k0 += BK) {
#pragma unroll
        for (int q = tid; q < A4; q += 256) {
            int row = q / (BK / 4);
            int c4 = (q % (BK / 4)) * 4;
            int gr = row0 + row;
            float4 v = make_float4(0.f, 0.f, 0.f, 0.f);
            if (gr < n) v = *(const float4*)(A + (size_t)gr * FI + k0 + c4);
            As[c4 + 0][row] = v.x;
            As[c4 + 1][row] = v.y;
            As[c4 + 2][row] = v.z;
            As[c4 + 3][row] = v.w;
        }
#pragma unroll
        for (int q = tid; q < W4; q += 256) {
            int kk = q / (FO / 4);
            int c4 = (q % (FO / 4)) * 4;
            *(float4*)&Ws[kk][c4] = *(const float4*)(W + (size_t)(k0 + kk) * FO + c4);
        }
        __syncthreads();

#pragma unroll
        for (int kk = 0; kk < BK; kk++) {
            unsigned long long a2[TM];
#pragma unroll
            for (int r = 0; r < TM; r++) {
                float a = As[kk][ty * TM + r];
                a2[r] = pack2(a, a);
            }
#pragma unroll
            for (int c2 = 0; c2 < NC2; c2++) {
                unsigned long long b2 =
                    *(const unsigned long long*)&Ws[kk][tx * TN + 2 * c2];
#pragma unroll
                for (int r = 0; r < TM; r++) FMA_F32X2(acc2[r][c2], a2[r], b2);
            }
        }
        __syncthreads();
    }

#pragma unroll
    for (int r = 0; r < TM; r++) {
        int gr = row0 + ty * TM + r;
        if (gr < n) {
            float* crow = C + (size_t)gr * FO + tx * TN;
#pragma unroll
            for (int c2 = 0; c2 < NC2; c2++) {
                float lo, hi;
                unpack2(acc2[r][c2], lo, hi);
                if constexpr (BIAS) {
                    lo += bias[tx * TN + 2 * c2];
                    hi += bias[tx * TN + 2 * c2 + 1];
                }
                crow[2 * c2] = lo;
                crow[2 * c2 + 1] = hi;
            }
        }
    }
}

// ============================================================================
// Aggregation: one warp per node; g_a[i] = relu(bias + dinv^2*g_h[i] + sum w*g_h[src])
// ============================================================================
__global__ void __launch_bounds__(256)
agg_kernel(const float* __restrict__ bias) {
    int warp = (blockIdx.x * blockDim.x + threadIdx.x) >> 5;
    int lane = threadIdx.x & 31;
    if (warp >= NN) return;
    const float* h = (const float*)g_h;
    float* out = (float*)g_a;
    int i = warp;
    float di = g_dinv[i];
    float self = di * di;
    const float* hi_ = h + (size_t)i * 96;
    float a0 = self * hi_[lane];
    float a1 = self * hi_[lane + 32];
    float a2 = self * hi_[lane + 64];
    int e = g_rowptr[i];
    int fin = g_rowptr[i + 1];
#pragma unroll 4
    for (; e < fin; e++) {
        int2 cw = g_cw[e];
        int s = cw.x;
        float w = __int_as_float(cw.y);
        const float* hr = h + (size_t)s * 96;
        a0 = fmaf(w, hr[lane], a0);
        a1 = fmaf(w, hr[lane + 32], a1);
        a2 = fmaf(w, hr[lane + 64], a2);
    }
    float* o = out + (size_t)i * 96;
    o[lane]      = fmaxf(a0 + bias[lane], 0.f);
    o[lane + 32] = fmaxf(a1 + bias[lane + 32], 0.f);
    o[lane + 64] = fmaxf(a2 + bias[lane + 64], 0.f);
}

// ============================================================================
// launch — pure kernel launches only (graph-capture safe)
// ============================================================================
extern "C" void kernel_launch(void* const* d_in, const int* in_sizes, int n_in,
                              void* d_out, int out_size) {
    const float* x    = (const float*)d_in[0];
    const int*   ei   = (const int*)d_in[1];
    const float* W1   = (const float*)d_in[2];
    const float* b1   = (const float*)d_in[3];
    const float* W2   = (const float*)d_in[4];
    const float* b2   = (const float*)d_in[5];
    const float* Wout = (const float*)d_in[6];
    const float* bout = (const float*)d_in[7];
    float* out = (float*)d_out;

    const int* src = ei;       // edge_index[0]
    const int* dst = ei + EE;  // edge_index[1]

    const int count_blocks = (EE + 255) / 256;          // 3125
    const int fill_blocks  = (EE / 2 + 255) / 256;      // 1563
    const int gemm_blocks  = (NN + 127) / 128;          // 391
    const int agg_blocks   = (NN * 32 + 255) / 256;     // 6250

    // ---- CSR build ----
    zero_deg_kernel<<<(NN + 1023) / 1024, 1024>>>();
    count_kernel<<<count_blocks, 256>>>(dst);
    scan_kernel<<<1, 1024>>>();
    fill_kernel<<<fill_blocks, 256>>>(src, dst);

    // ---- layer 1: x @ W1 -> g_h ; agg+b1, relu -> g_a ----
    gemm_kernel<128, 96, 16, 6, 16, 8, false>
        <<<gemm_blocks, 256>>>(x, W1, nullptr, nullptr, NN);
    agg_kernel<<<agg_blocks, 256>>>(b1);

    // ---- layer 2 ----
    gemm_kernel<96, 96, 16, 6, 16, 8, false>
        <<<gemm_blocks, 256>>>(nullptr, W2, nullptr, nullptr, NN);
    agg_kernel<<<agg_blocks, 256>>>(b2);

    // ---- output projection ----
    gemm_kernel<96, 40, 4, 10, 64, 2, true>
        <<<gemm_blocks, 256>>>(nullptr, Wout, bout, out, NN);
}

// round 9
// speedup vs baseline: 1.0167x; 1.0167x over previous
#include <cuda_runtime.h>

// ============================================================================
// FastAsyncGNN: 3-layer GCN
//   zero-deg -> [GEMM1 || edge-count] -> scan -> fill -> agg1
//   -> GEMM2 -> agg2 -> GEMM3(+bias)
// Shapes: N=50000, E=800000, F_IN=128, F_HID=96, F_OUT=40
// ============================================================================

#define NN 50000
#define EE 800000
#define GEMM1_BLOCKS 391   // ceil(50000/128)

// -------- scratch (device globals; no allocation allowed) --------
__device__ int   g_deg[NN];        // raw in-edge count (no self loop)
__device__ int   g_cur[NN];        // fill cursors
__device__ int   g_rowptr[NN + 1]; // CSR row pointers (real edges only)
__device__ float g_dinv[NN];       // rsqrt(deg+1)
__device__ __align__(8)  int2  g_cw[EE];      // (src, wgt-bits) per CSR slot
__device__ __align__(16) float g_h[NN * 96];  // GEMM output buffer
__device__ __align__(16) float g_a[NN * 96];  // aggregated/activated buffer

// ============================================================================
// CSR build pieces
// ============================================================================
__global__ void zero_deg_kernel() {
    int i = blockIdx.x * blockDim.x + threadIdx.x;
    if (i < NN) g_deg[i] = 0;
}

// single block, 1024 threads: exclusive scan of deg; dinv; zero cursors
__global__ void scan_kernel() {
    __shared__ int s[1024];
    int tid = threadIdx.x;
    const int per = (NN + 1023) / 1024;  // 49
    int start = tid * per;
    int end = start + per; if (end > NN) end = NN;
    int sum = 0;
    for (int i = start; i < end; i++) sum += g_deg[i];
    s[tid] = sum;
    __syncthreads();
    for (int off = 1; off < 1024; off <<= 1) {
        int v = s[tid];
        int u = (tid >= off) ? s[tid - off] : 0;
        __syncthreads();
        s[tid] = v + u;
        __syncthreads();
    }
    int run = (tid > 0) ? s[tid - 1] : 0;
    for (int i = start; i < end; i++) {
        g_rowptr[i] = run;
        run += g_deg[i];
        g_dinv[i] = rsqrtf((float)(g_deg[i] + 1));
        g_cur[i] = 0;
    }
    if (tid == 1023) g_rowptr[NN] = s[1023];
}

// 2 edges per thread (independent latency chains), int2 coalesced loads
__global__ void fill_kernel(const int* __restrict__ src, const int* __restrict__ dst) {
    int t = blockIdx.x * blockDim.x + threadIdx.x;
    int e0 = t * 2;
    if (e0 + 1 < EE) {
        int2 sp = *(const int2*)(src + e0);
        int2 dp = *(const int2*)(dst + e0);
        int p0 = atomicAdd(&g_cur[dp.x], 1);
        int p1 = atomicAdd(&g_cur[dp.y], 1);
        int o0 = g_rowptr[dp.x] + p0;
        int o1 = g_rowptr[dp.y] + p1;
        g_cw[o0] = make_int2(sp.x, __float_as_int(g_dinv[sp.x] * g_dinv[dp.x]));
        g_cw[o1] = make_int2(sp.y, __float_as_int(g_dinv[sp.y] * g_dinv[dp.y]));
    } else if (e0 < EE) {
        int sN = src[e0];
        int d = dst[e0];
        int p = atomicAdd(&g_cur[d], 1);
        g_cw[g_rowptr[d] + p] = make_int2(sN, __float_as_int(g_dinv[sN] * g_dinv[d]));
    }
}

// ============================================================================
// GEMM body: C[n,FO] = A[n,FI] @ W[FI,FO] (+bias), scalar FFMA inner loop.
// BM = RT*TM = 128 rows, BK = 32.
// ============================================================================
template <int FI, int FO, int CT, int TN, int RT, int TM, bool BIAS>
__device__ __forceinline__ void gemm_body(
    const float* __restrict__ A, const float* __restrict__ W,
    const float* __restrict__ bias, float* __restrict__ C, int n, int bx) {
    constexpr int BM = RT * TM;  // 128
    constexpr int BK = 32;
    static_assert(CT * RT == 256, "thread shape");
    static_assert(CT * TN == FO, "col coverage");
    static_assert(FO % 4 == 0, "W vec4 staging");

    __shared__ float As[BK][BM + 1];   // [kk][row]
    __shared__ float Ws[BK][FO];       // [kk][col]

    int tid = threadIdx.x;
    int tx = tid % CT;
    int ty = tid / CT;
    int row0 = bx * BM;

    float acc[TM][TN];
#pragma unroll
    for (int r = 0; r < TM; r++)
#pragma unroll
        for (int c = 0; c < TN; c++) acc[r][c] = 0.f;

    constexpr int A4 = BM * (BK / 4);   // float4s in A tile
    constexpr int W4 = BK * (FO / 4);   // float4s in W tile

    for (int k0 = 0; k0 < FI; k0 += BK) {
#pragma unroll
        for (int q = tid; q < A4; q += 256) {
            int row = q / (BK / 4);
            int c4 = (q % (BK / 4)) * 4;
            int gr = row0 + row;
            float4 v = make_float4(0.f, 0.f, 0.f, 0.f);
            if (gr < n) v = *(const float4*)(A + (size_t)gr * FI + k0 + c4);
            As[c4 + 0][row] = v.x;
            As[c4 + 1][row] = v.y;
            As[c4 + 2][row] = v.z;
            As[c4 + 3][row] = v.w;
        }
#pragma unroll
        for (int q = tid; q < W4; q += 256) {
            int kk = q / (FO / 4);
            int c4 = (q % (FO / 4)) * 4;
            *(float4*)&Ws[kk][c4] = *(const float4*)(W + (size_t)(k0 + kk) * FO + c4);
        }
        __syncthreads();

#pragma unroll
        for (int kk = 0; kk < BK; kk++) {
            float av[TM];
#pragma unroll
            for (int r = 0; r < TM; r++) av[r] = As[kk][ty * TM + r];
            float bv[TN];
#pragma unroll
            for (int c = 0; c < TN; c++) bv[c] = Ws[kk][tx * TN + c];
#pragma unroll
            for (int c = 0; c < TN; c++)
#pragma unroll
                for (int r = 0; r < TM; r++)
                    acc[r][c] = fmaf(av[r], bv[c], acc[r][c]);
        }
        __syncthreads();
    }

#pragma unroll
    for (int r = 0; r < TM; r++) {
        int gr = row0 + ty * TM + r;
        if (gr < n) {
            float* crow = C + (size_t)gr * FO + tx * TN;
#pragma unroll
            for (int c = 0; c < TN; c++) {
                float v = acc[r][c];
                if constexpr (BIAS) v += bias[tx * TN + c];
                crow[c] = v;
            }
        }
    }
}

// plain GEMM kernel (layers 2/3)
template <int FI, int FO, int CT, int TN, int RT, int TM, bool BIAS>
__global__ void __launch_bounds__(256)
gemm_kernel(const float* __restrict__ A_, const float* __restrict__ W,
            const float* __restrict__ bias, float* __restrict__ C_, int n) {
    const float* A = A_ ? A_ : (const float*)g_a;
    float* C = C_ ? C_ : (float*)g_h;
    gemm_body<FI, FO, CT, TN, RT, TM, BIAS>(A, W, bias, C, n, blockIdx.x);
}

// fused: blocks [0, GEMM1_BLOCKS) do GEMM1 tiles; the rest count in-degrees.
// GEMM1 uses FMA pipe + smem; count uses LTS atomics — complementary pipes.
__global__ void __launch_bounds__(256)
gemm1_count_kernel(const float* __restrict__ x, const float* __restrict__ W1,
                   const int* __restrict__ dst) {
    if (blockIdx.x < GEMM1_BLOCKS) {
        gemm_body<128, 96, 16, 6, 16, 8, false>(x, W1, nullptr, (float*)g_h, NN,
                                                blockIdx.x);
    } else {
        int e = (blockIdx.x - GEMM1_BLOCKS) * 256 + threadIdx.x;
        if (e < EE) atomicAdd(&g_deg[dst[e]], 1);
    }
}

// ============================================================================
// Aggregation: one warp per node; g_a[i] = relu(bias + dinv^2*g_h[i] + sum w*g_h[src])
// ============================================================================
__global__ void __launch_bounds__(256)
agg_kernel(const float* __restrict__ bias) {
    int warp = (blockIdx.x * blockDim.x + threadIdx.x) >> 5;
    int lane = threadIdx.x & 31;
    if (warp >= NN) return;
    const float* h = (const float*)g_h;
    float* out = (float*)g_a;
    int i = warp;
    float di = g_dinv[i];
    float self = di * di;
    const float* hi_ = h + (size_t)i * 96;
    float a0 = self * hi_[lane];
    float a1 = self * hi_[lane + 32];
    float a2 = self * hi_[lane + 64];
    int e = g_rowptr[i];
    int fin = g_rowptr[i + 1];
#pragma unroll 4
    for (; e < fin; e++) {
        int2 cw = g_cw[e];
        int s = cw.x;
        float w = __int_as_float(cw.y);
        const float* hr = h + (size_t)s * 96;
        a0 = fmaf(w, hr[lane], a0);
        a1 = fmaf(w, hr[lane + 32], a1);
        a2 = fmaf(w, hr[lane + 64], a2);
    }
    float* o = out + (size_t)i * 96;
    o[lane]      = fmaxf(a0 + bias[lane], 0.f);
    o[lane + 32] = fmaxf(a1 + bias[lane + 32], 0.f);
    o[lane + 64] = fmaxf(a2 + bias[lane + 64], 0.f);
}

// ============================================================================
// launch — pure kernel launches only (graph-capture safe)
// ============================================================================
extern "C" void kernel_launch(void* const* d_in, const int* in_sizes, int n_in,
                              void* d_out, int out_size) {
    const float* x    = (const float*)d_in[0];
    const int*   ei   = (const int*)d_in[1];
    const float* W1   = (const float*)d_in[2];
    const float* b1   = (const float*)d_in[3];
    const float* W2   = (const float*)d_in[4];
    const float* b2   = (const float*)d_in[5];
    const float* Wout = (const float*)d_in[6];
    const float* bout = (const float*)d_in[7];
    float* out = (float*)d_out;

    const int* src = ei;       // edge_index[0]
    const int* dst = ei + EE;  // edge_index[1]

    const int count_blocks = (EE + 255) / 256;          // 3125
    const int fill_blocks  = (EE / 2 + 255) / 256;      // 1563
    const int gemm_blocks  = GEMM1_BLOCKS;              // 391
    const int agg_blocks   = (NN * 32 + 255) / 256;     // 6250

    // ---- CSR build overlapped with layer-1 transform ----
    zero_deg_kernel<<<(NN + 1023) / 1024, 1024>>>();
    gemm1_count_kernel<<<gemm_blocks + count_blocks, 256>>>(x, W1, dst);
    scan_kernel<<<1, 1024>>>();
    fill_kernel<<<fill_blocks, 256>>>(src, dst);

    // ---- layer 1 aggregation ----
    agg_kernel<<<agg_blocks, 256>>>(b1);

    // ---- layer 2 ----
    gemm_kernel<96, 96, 16, 6, 16, 8, false>
        <<<gemm_blocks, 256>>>(nullptr, W2, nullptr, nullptr, NN);
    agg_kernel<<<agg_blocks, 256>>>(b2);

    // ---- output projection ----
    gemm_kernel<96, 40, 8, 5, 32, 4, true>
        <<<gemm_blocks, 256>>>(nullptr, Wout, bout, out, NN);
}

// round 10
// speedup vs baseline: 1.1389x; 1.1201x over previous
#include <cuda_runtime.h>
#include <mma.h>

using namespace nvcuda;

// ============================================================================
// FastAsyncGNN: 3-layer GCN
//   zero-deg -> count -> scan -> fill -> [TF32-GEMM -> agg]x2 -> GEMM3(+bias)
// Shapes: N=50000, E=800000, F_IN=128, F_HID=96, F_OUT=40
// ============================================================================

#define NN 50000
#define EE 800000
#define NPAD 50048   // 391 blocks * 128 rows — wmma stores go up to here

// -------- scratch (device globals; no allocation allowed) --------
__device__ int   g_deg[NN];        // raw in-edge count (no self loop)
__device__ int   g_cur[NN];        // fill cursors
__device__ int   g_rowptr[NN + 1]; // CSR row pointers (real edges only)
__device__ float g_dinv[NN];       // rsqrt(deg+1)
__device__ __align__(8)  int2  g_cw[EE];        // (src, wgt-bits) per CSR slot
__device__ __align__(16) float g_h[NPAD * 96];  // GEMM output (padded for wmma tail)
__device__ __align__(16) float g_a[NN * 96];    // aggregated/activated buffer

// ============================================================================
// CSR build
// ============================================================================
__global__ void zero_deg_kernel() {
    int i = blockIdx.x * blockDim.x + threadIdx.x;
    if (i < NN) g_deg[i] = 0;
}

__global__ void count_kernel(const int* __restrict__ dst) {
    int e = blockIdx.x * blockDim.x + threadIdx.x;
    if (e < EE) atomicAdd(&g_deg[dst[e]], 1);
}

// single block, 1024 threads: exclusive scan of deg; dinv; zero cursors
__global__ void scan_kernel() {
    __shared__ int s[1024];
    int tid = threadIdx.x;
    const int per = (NN + 1023) / 1024;  // 49
    int start = tid * per;
    int end = start + per; if (end > NN) end = NN;
    int sum = 0;
    for (int i = start; i < end; i++) sum += g_deg[i];
    s[tid] = sum;
    __syncthreads();
    for (int off = 1; off < 1024; off <<= 1) {
        int v = s[tid];
        int u = (tid >= off) ? s[tid - off] : 0;
        __syncthreads();
        s[tid] = v + u;
        __syncthreads();
    }
    int run = (tid > 0) ? s[tid - 1] : 0;
    for (int i = start; i < end; i++) {
        g_rowptr[i] = run;
        run += g_deg[i];
        g_dinv[i] = rsqrtf((float)(g_deg[i] + 1));
        g_cur[i] = 0;
    }
    if (tid == 1023) g_rowptr[NN] = s[1023];
}

// 2 edges per thread (independent latency chains), int2 coalesced loads
__global__ void fill_kernel(const int* __restrict__ src, const int* __restrict__ dst) {
    int t = blockIdx.x * blockDim.x + threadIdx.x;
    int e0 = t * 2;
    if (e0 + 1 < EE) {
        int2 sp = *(const int2*)(src + e0);
        int2 dp = *(const int2*)(dst + e0);
        int p0 = atomicAdd(&g_cur[dp.x], 1);
        int p1 = atomicAdd(&g_cur[dp.y], 1);
        int o0 = g_rowptr[dp.x] + p0;
        int o1 = g_rowptr[dp.y] + p1;
        g_cw[o0] = make_int2(sp.x, __float_as_int(g_dinv[sp.x] * g_dinv[dp.x]));
        g_cw[o1] = make_int2(sp.y, __float_as_int(g_dinv[sp.y] * g_dinv[dp.y]));
    } else if (e0 < EE) {
        int sN = src[e0];
        int d = dst[e0];
        int p = atomicAdd(&g_cur[d], 1);
        g_cw[g_rowptr[d] + p] = make_int2(sN, __float_as_int(g_dinv[sN] * g_dinv[d]));
    }
}

// ============================================================================
// TF32 tensor-core GEMM: g_h[n,FO] = A[n,FI] @ W[FI,FO]
// A_==nullptr -> read from g_a. Output always g_h (padded to NPAD rows).
// BM=128 rows/block, BK=32, 8 warps: warp w owns rows [w*16, w*16+16) x FO.
// FI % 32 == 0, FO % 16 == 0.
// ============================================================================
template <int FI, int FO>
__global__ void __launch_bounds__(256)
gemm_tc_kernel(const float* __restrict__ A_, const float* __restrict__ W, int n) {
    constexpr int BM = 128;
    constexpr int BK = 32;
    constexpr int NT = FO / 16;      // col tiles (6 for FO=96)
    constexpr int LDA = BK + 4;      // 36 floats = 144B, multiple of 16B
    static_assert(FI % BK == 0 && FO % 16 == 0, "shape");

    const float* A = A_ ? A_ : (const float*)g_a;
    float* C = (float*)g_h;

    __shared__ float As[BM][LDA];    // row-major A tile (tf32-converted)
    __shared__ float Ws[BK][FO];     // row-major W tile (tf32-converted)

    int tid = threadIdx.x;
    int warp = tid >> 5;
    int row0 = blockIdx.x * BM;

    wmma::fragment<wmma::accumulator, 16, 16, 8, float> acc[NT];
#pragma unroll
    for (int t = 0; t < NT; t++) wmma::fill_fragment(acc[t], 0.f);

    for (int k0 = 0; k0 < FI; k0 += BK) {
        // stage A tile (convert to tf32)
#pragma unroll
        for (int q = tid; q < BM * (BK / 4); q += 256) {
            int row = q / (BK / 4);
            int c4 = (q % (BK / 4)) * 4;
            int gr = row0 + row;
            float4 v = make_float4(0.f, 0.f, 0.f, 0.f);
            if (gr < n) v = *(const float4*)(A + (size_t)gr * FI + k0 + c4);
            As[row][c4 + 0] = wmma::__float_to_tf32(v.x);
            As[row][c4 + 1] = wmma::__float_to_tf32(v.y);
            As[row][c4 + 2] = wmma::__float_to_tf32(v.z);
            As[row][c4 + 3] = wmma::__float_to_tf32(v.w);
        }
        // stage W tile (convert to tf32)
#pragma unroll
        for (int q = tid; q < BK * (FO / 4); q += 256) {
            int kk = q / (FO / 4);
            int c4 = (q % (FO / 4)) * 4;
            float4 v = *(const float4*)(W + (size_t)(k0 + kk) * FO + c4);
            Ws[kk][c4 + 0] = wmma::__float_to_tf32(v.x);
            Ws[kk][c4 + 1] = wmma::__float_to_tf32(v.y);
            Ws[kk][c4 + 2] = wmma::__float_to_tf32(v.z);
            Ws[kk][c4 + 3] = wmma::__float_to_tf32(v.w);
        }
        __syncthreads();

#pragma unroll
        for (int ks = 0; ks < BK; ks += 8) {
            wmma::fragment<wmma::matrix_a, 16, 16, 8, wmma::precision::tf32,
                           wmma::row_major> af;
            wmma::load_matrix_sync(af, &As[warp * 16][ks], LDA);
#pragma unroll
            for (int t = 0; t < NT; t++) {
                wmma::fragment<wmma::matrix_b, 16, 16, 8, wmma::precision::tf32,
                               wmma::row_major> bf;
                wmma::load_matrix_sync(bf, &Ws[ks][t * 16], FO);
                wmma::mma_sync(acc[t], af, bf, acc[t]);
            }
        }
        __syncthreads();
    }

    // store (rows may exceed n but stay < NPAD — padded buffer)
    size_t gr = (size_t)(row0 + warp * 16);
#pragma unroll
    for (int t = 0; t < NT; t++)
        wmma::store_matrix_sync(C + gr * FO + t * 16, acc[t], FO,
                                wmma::mem_row_major);
}

// ============================================================================
// Scalar GEMM (output projection, FO=40): out = g_a @ W + bias
// ============================================================================
template <int FI, int FO, int CT, int TN, int RT, int TM>
__global__ void __launch_bounds__(256)
gemm_scalar_kernel(const float* __restrict__ W, const float* __restrict__ bias,
                   float* __restrict__ C, int n) {
    constexpr int BM = RT * TM;  // 128
    constexpr int BK = 32;
    static_assert(CT * RT == 256 && CT * TN == FO && FO % 4 == 0, "shape");

    const float* A = (const float*)g_a;

    __shared__ float As[BK][BM + 1];
    __shared__ float Ws[BK][FO];

    int tid = threadIdx.x;
    int tx = tid % CT;
    int ty = tid / CT;
    int row0 = blockIdx.x * BM;

    float acc[TM][TN];
#pragma unroll
    for (int r = 0; r < TM; r++)
#pragma unroll
        for (int c = 0; c < TN; c++) acc[r][c] = 0.f;

    constexpr int A4 = BM * (BK / 4);
    constexpr int W4 = BK * (FO / 4);

    for (int k0 = 0; k0 < FI; k0 += BK) {
#pragma unroll
        for (int q = tid; q < A4; q += 256) {
            int row = q / (BK / 4);
            int c4 = (q % (BK / 4)) * 4;
            int gr = row0 + row;
            float4 v = make_float4(0.f, 0.f, 0.f, 0.f);
            if (gr < n) v = *(const float4*)(A + (size_t)gr * FI + k0 + c4);
            As[c4 + 0][row] = v.x;
            As[c4 + 1][row] = v.y;
            As[c4 + 2][row] = v.z;
            As[c4 + 3][row] = v.w;
        }
#pragma unroll
        for (int q = tid; q < W4; q += 256) {
            int kk = q / (FO / 4);
            int c4 = (q % (FO / 4)) * 4;
            *(float4*)&Ws[kk][c4] = *(const float4*)(W + (size_t)(k0 + kk) * FO + c4);
        }
        __syncthreads();

#pragma unroll
        for (int kk = 0; kk < BK; kk++) {
            float av[TM];
#pragma unroll
            for (int r = 0; r < TM; r++) av[r] = As[kk][ty * TM + r];
            float bv[TN];
#pragma unroll
            for (int c = 0; c < TN; c++) bv[c] = Ws[kk][tx * TN + c];
#pragma unroll
            for (int c = 0; c < TN; c++)
#pragma unroll
                for (int r = 0; r < TM; r++)
                    acc[r][c] = fmaf(av[r], bv[c], acc[r][c]);
        }
        __syncthreads();
    }

#pragma unroll
    for (int r = 0; r < TM; r++) {
        int gr = row0 + ty * TM + r;
        if (gr < n) {
            float* crow = C + (size_t)gr * FO + tx * TN;
#pragma unroll
            for (int c = 0; c < TN; c++)
                crow[c] = acc[r][c] + bias[tx * TN + c];
        }
    }
}

// ============================================================================
// Aggregation: one warp per node; g_a[i] = relu(bias + dinv^2*g_h[i] + sum w*g_h[src])
// ============================================================================
__global__ void __launch_bounds__(256)
agg_kernel(const float* __restrict__ bias) {
    int warp = (blockIdx.x * blockDim.x + threadIdx.x) >> 5;
    int lane = threadIdx.x & 31;
    if (warp >= NN) return;
    const float* h = (const float*)g_h;
    float* out = (float*)g_a;
    int i = warp;
    float di = g_dinv[i];
    float self = di * di;
    const float* hi_ = h + (size_t)i * 96;
    float a0 = self * hi_[lane];
    float a1 = self * hi_[lane + 32];
    float a2 = self * hi_[lane + 64];
    int e = g_rowptr[i];
    int fin = g_rowptr[i + 1];
#pragma unroll 4
    for (; e < fin; e++) {
        int2 cw = g_cw[e];
        int s = cw.x;
        float w = __int_as_float(cw.y);
        const float* hr = h + (size_t)s * 96;
        a0 = fmaf(w, hr[lane], a0);
        a1 = fmaf(w, hr[lane + 32], a1);
        a2 = fmaf(w, hr[lane + 64], a2);
    }
    float* o = out + (size_t)i * 96;
    o[lane]      = fmaxf(a0 + bias[lane], 0.f);
    o[lane + 32] = fmaxf(a1 + bias[lane + 32], 0.f);
    o[lane + 64] = fmaxf(a2 + bias[lane + 64], 0.f);
}

// ============================================================================
// launch — pure kernel launches only (graph-capture safe)
// ============================================================================
extern "C" void kernel_launch(void* const* d_in, const int* in_sizes, int n_in,
                              void* d_out, int out_size) {
    const float* x    = (const float*)d_in[0];
    const int*   ei   = (const int*)d_in[1];
    const float* W1   = (const float*)d_in[2];
    const float* b1   = (const float*)d_in[3];
    const float* W2   = (const float*)d_in[4];
    const float* b2   = (const float*)d_in[5];
    const float* Wout = (const float*)d_in[6];
    const float* bout = (const float*)d_in[7];
    float* out = (float*)d_out;

    const int* src = ei;       // edge_index[0]
    const int* dst = ei + EE;  // edge_index[1]

    const int count_blocks = (EE + 255) / 256;          // 3125
    const int fill_blocks  = (EE / 2 + 255) / 256;      // 1563
    const int gemm_blocks  = (NN + 127) / 128;          // 391
    const int agg_blocks   = (NN * 32 + 255) / 256;     // 6250

    // ---- CSR build ----
    zero_deg_kernel<<<(NN + 1023) / 1024, 1024>>>();
    count_kernel<<<count_blocks, 256>>>(dst);
    scan_kernel<<<1, 1024>>>();
    fill_kernel<<<fill_blocks, 256>>>(src, dst);

    // ---- layer 1: x @ W1 -> g_h (tf32 tensor) ; agg+b1, relu -> g_a ----
    gemm_tc_kernel<128, 96><<<gemm_blocks, 256>>>(x, W1, NN);
    agg_kernel<<<agg_blocks, 256>>>(b1);

    // ---- layer 2: g_a @ W2 -> g_h (tf32 tensor) ; agg+b2, relu -> g_a ----
    gemm_tc_kernel<96, 96><<<gemm_blocks, 256>>>(nullptr, W2, NN);
    agg_kernel<<<agg_blocks, 256>>>(b2);

    // ---- output projection (scalar fp32, exact) ----
    gemm_scalar_kernel<96, 40, 8, 5, 32, 4>
        <<<gemm_blocks, 256>>>(Wout, bout, out, NN);
}